// round 16
// baseline (speedup 1.0000x reference)
#include <cuda_runtime.h>
#include <cuda_fp16.h>
#include <cstdint>
#include <cstddef>

#define S_LEN 2048
#define HID   4096
#define NH    32
#define HD    128
#define P3    12288   // 3*HID
#define NORM  0.08838834764831845f   // 1/sqrt(128)

// ---------------- scratch (no allocations allowed) ----------------
__device__ float  g_proj[S_LEN * P3];
__device__ __half g_hid_h[S_LEN * HID];
__device__ __half g_wp_h[P3 * HID];
__device__ __half g_wo_h[HID * HID];
__device__ __half g_attn_h[S_LEN * HID];

// ---------------- helpers ----------------
__device__ __forceinline__ uint32_t smem_u32(const void* p) {
    uint32_t a;
    asm("{ .reg .u64 t; cvta.to.shared.u64 t, %1; cvt.u32.u64 %0, t; }" : "=r"(a) : "l"(p));
    return a;
}
__device__ __forceinline__ void cp16(uint32_t saddr, const void* gptr) {
    asm volatile("cp.async.ca.shared.global [%0], [%1], 16;" :: "r"(saddr), "l"(gptr));
}
#define CP_COMMIT() asm volatile("cp.async.commit_group;" ::: "memory")
#define CP_WAIT(n)  asm volatile("cp.async.wait_group %0;" :: "n"(n) : "memory")

__device__ __forceinline__ void ldsm4(uint32_t& r0, uint32_t& r1, uint32_t& r2, uint32_t& r3,
                                      uint32_t addr) {
    asm volatile("ldmatrix.sync.aligned.m8n8.x4.shared.b16 {%0,%1,%2,%3}, [%4];"
                 : "=r"(r0), "=r"(r1), "=r"(r2), "=r"(r3) : "r"(addr));
}

// mma.sync m16n8k16 fp16, fp32 accum
__device__ __forceinline__ void mma_fp16(float& c0, float& c1, float& c2, float& c3,
                                         uint32_t a0, uint32_t a1, uint32_t a2, uint32_t a3,
                                         uint32_t b0, uint32_t b1) {
    asm volatile(
        "mma.sync.aligned.m16n8k16.row.col.f32.f16.f16.f32 "
        "{%0,%1,%2,%3}, {%4,%5,%6,%7}, {%8,%9}, {%0,%1,%2,%3};"
        : "+f"(c0), "+f"(c1), "+f"(c2), "+f"(c3)
        : "r"(a0), "r"(a1), "r"(a2), "r"(a3), "r"(b0), "r"(b1));
}
// mma.sync m16n8k16 bf16 (attention)
__device__ __forceinline__ void mma_bf16(float& c0, float& c1, float& c2, float& c3,
                                         uint32_t a0, uint32_t a1, uint32_t a2, uint32_t a3,
                                         uint32_t b0, uint32_t b1) {
    asm volatile(
        "mma.sync.aligned.m16n8k16.row.col.f32.bf16.bf16.f32 "
        "{%0,%1,%2,%3}, {%4,%5,%6,%7}, {%8,%9}, {%0,%1,%2,%3};"
        : "+f"(c0), "+f"(c1), "+f"(c2), "+f"(c3)
        : "r"(a0), "r"(a1), "r"(a2), "r"(a3), "r"(b0), "r"(b1));
}
__device__ __forceinline__ void split_pair(float x0, float x1, uint32_t& hp, uint32_t& lp) {
    uint16_t h0, h1, l0, l1;
    asm("cvt.rn.bf16.f32 %0, %1;" : "=h"(h0) : "f"(x0));
    asm("cvt.rn.bf16.f32 %0, %1;" : "=h"(h1) : "f"(x1));
    float r0 = x0 - __uint_as_float((uint32_t)h0 << 16);
    float r1 = x1 - __uint_as_float((uint32_t)h1 << 16);
    asm("cvt.rn.bf16.f32 %0, %1;" : "=h"(l0) : "f"(r0));
    asm("cvt.rn.bf16.f32 %0, %1;" : "=h"(l1) : "f"(r1));
    asm("mov.b32 %0, {%1, %2};" : "=r"(hp) : "h"(h0), "h"(h1));
    asm("mov.b32 %0, {%1, %2};" : "=r"(lp) : "h"(l0), "h"(l1));
}

// ---------------- fp32 -> fp16 convert ----------------
__global__ __launch_bounds__(256) void f2h_kernel(const float* __restrict__ src,
                                                  __half* __restrict__ dst, int n) {
    int i = (blockIdx.x * blockDim.x + threadIdx.x) * 8;
    if (i >= n) return;
    float4 a = *(const float4*)(src + i);
    float4 b = *(const float4*)(src + i + 4);
    __half2 h0 = __floats2half2_rn(a.x, a.y);
    __half2 h1 = __floats2half2_rn(a.z, a.w);
    __half2 h2 = __floats2half2_rn(b.x, b.y);
    __half2 h3 = __floats2half2_rn(b.z, b.w);
    uint4 v = {*(uint32_t*)&h0, *(uint32_t*)&h1, *(uint32_t*)&h2, *(uint32_t*)&h3};
    *(uint4*)(dst + i) = v;
}

// ---------------- fp16 cp.async + ldmatrix GEMM: C = A * B^T ----------------
// Block 128x128x32, 128 threads (4 warps 2x2), warp tile 64x64, 4-stage cp.async,
// 2 CTAs/SM: independent barrier domains overlap LDSM/barrier phases across CTAs.
#define KW    20
#define NSTG  4
#define AW    (128 * KW)                       // A words per stage
#define STGW  ((128 + 128) * KW)               // 5120 words per stage
#define GEMM_SMEM (NSTG * STGW * 4)            // 81920 B

__global__ __launch_bounds__(128, 2) void gemm_fp16ca(const __half* __restrict__ A,
                                                      const __half* __restrict__ B,
                                                      float* __restrict__ C,
                                                      int M, int N, int K) {
    extern __shared__ uint32_t sm[];
    const int t = threadIdx.x;
    const int w = t >> 5, lane = t & 31;
    const int wm = w >> 1, wn = w & 1;         // 2x2 warp grid, warp tile 64x64
    const int g = lane >> 2, cc = lane & 3;
    const int m0 = blockIdx.y * 128, n0 = blockIdx.x * 128;
    const int KT = K >> 5;
    const uint32_t sbase = smem_u32(sm);

    // cp.async: thread t covers full row t of A and of B (4 chunks each)
    const __half* AgA = A + (size_t)(m0 + t) * K;
    const __half* BgB = B + (size_t)(n0 + t) * K;
    const uint32_t saA = sbase + (t * KW) * 4;
    const uint32_t saB = saA + AW * 4;

    // ldmatrix per-lane word offsets (within stage)
    const int lrow = lane & 7, sel = lane >> 3;
    uint32_t a_woff[4], b_woff[4];
#pragma unroll
    for (int mt = 0; mt < 4; mt++)
        a_woff[mt] = (uint32_t)((wm * 64 + mt * 16 + lrow + (sel & 1) * 8) * KW +
                                (sel >> 1) * 4);
#pragma unroll
    for (int p = 0; p < 4; p++)
        b_woff[p] = (uint32_t)(AW + (wn * 64 + p * 16 + (sel >> 1) * 8 + lrow) * KW +
                               (sel & 1) * 4);

    // prologue: stages 0..NSTG-2
#pragma unroll
    for (int s = 0; s < NSTG - 1; s++) {
        const uint32_t so = s * STGW * 4;
        const size_t ko = (size_t)s * 32;
#pragma unroll
        for (int c = 0; c < 4; c++) {
            cp16(saA + so + c * 16, AgA + ko + c * 8);
            cp16(saB + so + c * 16, BgB + ko + c * 8);
        }
        CP_COMMIT();
    }

    float acc[4][8][4];
#pragma unroll
    for (int mt = 0; mt < 4; mt++)
#pragma unroll
        for (int nt = 0; nt < 8; nt++)
#pragma unroll
            for (int q = 0; q < 4; q++) acc[mt][nt][q] = 0.f;

    for (int kt = 0; kt < KT; kt++) {
        CP_WAIT(2);
        __syncthreads();
        if (kt + NSTG - 1 < KT) {
            const uint32_t so = ((kt + NSTG - 1) % NSTG) * STGW * 4;
            const size_t ko = (size_t)(kt + NSTG - 1) * 32;
#pragma unroll
            for (int c = 0; c < 4; c++) {
                cp16(saA + so + c * 16, AgA + ko + c * 8);
                cp16(saB + so + c * 16, BgB + ko + c * 8);
            }
        }
        CP_COMMIT();

        const uint32_t stgoff = sbase + ((kt % NSTG) * STGW) * 4;
#pragma unroll
        for (int hh = 0; hh < 2; hh++) {
            const uint32_t kwb = stgoff + hh * 8 * 4;
            uint32_t af[4][4], bf[4][4];
#pragma unroll
            for (int mt = 0; mt < 4; mt++)
                ldsm4(af[mt][0], af[mt][1], af[mt][2], af[mt][3], kwb + a_woff[mt] * 4);
#pragma unroll
            for (int p = 0; p < 4; p++)
                ldsm4(bf[p][0], bf[p][1], bf[p][2], bf[p][3], kwb + b_woff[p] * 4);
#pragma unroll
            for (int mt = 0; mt < 4; mt++)
#pragma unroll
                for (int nt = 0; nt < 8; nt++)
                    mma_fp16(acc[mt][nt][0], acc[mt][nt][1], acc[mt][nt][2], acc[mt][nt][3],
                             af[mt][0], af[mt][1], af[mt][2], af[mt][3],
                             bf[nt >> 1][(nt & 1) * 2], bf[nt >> 1][(nt & 1) * 2 + 1]);
        }
    }

#pragma unroll
    for (int mt = 0; mt < 4; mt++) {
        const int r = m0 + wm * 64 + mt * 16 + g;
#pragma unroll
        for (int nt = 0; nt < 8; nt++) {
            const int n = n0 + wn * 64 + nt * 8 + 2 * cc;
            *(float2*)&C[(size_t)r * N + n]       = make_float2(acc[mt][nt][0], acc[mt][nt][1]);
            *(float2*)&C[(size_t)(r + 8) * N + n] = make_float2(acc[mt][nt][2], acc[mt][nt][3]);
        }
    }
}

// ---------------- RoPE ----------------
__global__ __launch_bounds__(256) void rope2_kernel(float* __restrict__ proj,
                                                    const int* __restrict__ pos_ids) {
    __shared__ float ca[64], sa[64];
    const int s = blockIdx.x;
    const int t = threadIdx.x;
    if (t < 64) {
        const int pos = pos_ids[s];
        double inv = exp(-((double)t / 64.0) * 9.210340371976184);
        double a = (double)pos * inv;
        const double twopi = 6.283185307179586476925286766559;
        a -= floor(a / twopi) * twopi;
        sa[t] = sinf((float)a);
        ca[t] = cosf((float)a);
    }
    __syncthreads();
    float* base = proj + (size_t)s * P3;
#pragma unroll
    for (int it = 0; it < 16; it++) {
        const int p = t + it * 256;
        const int d = p & 63;
        const int hh = (p >> 6) & 31;
        float* ptr = base + ((p >> 11) ? HID : 0) + hh * HD + d;
        const float x1 = ptr[0], x2 = ptr[64];
        const float c = ca[d], sn = sa[d];
        ptr[0]  = x1 * c - x2 * sn;
        ptr[64] = x2 * c + x1 * sn;
    }
}

// ---------------- register-resident bf16-split flash attention (R14, unchanged) ----------------
#define OFF_QH  0
#define OFF_QL  (OFF_QH + 128 * 136 * 2)
#define OFF_KH  (OFF_QL + 128 * 136 * 2)
#define OFF_KL  (OFF_KH + 64 * 136 * 2)
#define OFF_VTH (OFF_KL + 64 * 136 * 2)
#define OFF_VTL (OFF_VTH + 128 * 72 * 2)
#define ATTN3_SMEM (OFF_VTL + 128 * 72 * 2)   // 141312

__global__ __launch_bounds__(256, 1) void attn_reg(const float* __restrict__ proj,
                                                   __half* __restrict__ attn_out_h) {
    extern __shared__ char smraw[];
    uint32_t* Qh  = (uint32_t*)(smraw + OFF_QH);
    uint32_t* Ql  = (uint32_t*)(smraw + OFF_QL);
    uint32_t* Kh  = (uint32_t*)(smraw + OFF_KH);
    uint32_t* Kl  = (uint32_t*)(smraw + OFF_KL);
    uint32_t* Vth = (uint32_t*)(smraw + OFF_VTH);
    uint32_t* Vtl = (uint32_t*)(smraw + OFF_VTL);

    const int t = threadIdx.x;
    const int w = t >> 5, lane = t & 31;
    const int g = lane >> 2, cc = lane & 3;
    const int h = blockIdx.x;
    const int qt = 15 - (int)blockIdx.y;
    const int qbase = qt * 128;
    const int qcol = h * HD, kcol = HID + h * HD, vcol = 2 * HID + h * HD;

    {
        const int row = t >> 1;
        const int c0 = (t & 1) * 64;
        const float* src = proj + (size_t)(qbase + row) * P3 + qcol + c0;
        uint32_t* qh = Qh + row * 68 + (c0 >> 1);
        uint32_t* ql = Ql + row * 68 + (c0 >> 1);
#pragma unroll
        for (int i = 0; i < 16; i++) {
            float4 v = *(const float4*)(src + i * 4);
            uint32_t hp, lp;
            split_pair(v.x * NORM, v.y * NORM, hp, lp);
            qh[2 * i] = hp; ql[2 * i] = lp;
            split_pair(v.z * NORM, v.w * NORM, hp, lp);
            qh[2 * i + 1] = hp; ql[2 * i + 1] = lp;
        }
    }

    float rowM0 = -3.0e38f, rowM1 = -3.0e38f, rowL0 = 0.f, rowL1 = 0.f;
    float oacc[16][4];
#pragma unroll
    for (int nt = 0; nt < 16; nt++)
#pragma unroll
        for (int q = 0; q < 4; q++) oacc[nt][q] = 0.f;

    const int nkt = 2 * qt + 2;
    for (int j = 0; j < nkt; j++) {
        __syncthreads();
        {
            const int r = t >> 2;
            const int c0 = (t & 3) * 32;
            const float* src = proj + (size_t)(j * 64 + r) * P3 + kcol + c0;
            uint32_t* kh = Kh + r * 68 + (c0 >> 1);
            uint32_t* kl = Kl + r * 68 + (c0 >> 1);
#pragma unroll
            for (int i = 0; i < 8; i++) {
                float4 v = *(const float4*)(src + i * 4);
                uint32_t hp, lp;
                split_pair(v.x, v.y, hp, lp);
                kh[2 * i] = hp; kl[2 * i] = lp;
                split_pair(v.z, v.w, hp, lp);
                kh[2 * i + 1] = hp; kl[2 * i + 1] = lp;
            }
        }
        {
            const int c = (t & 31) + ((t >> 5) & 3) * 32;
            const int rp0 = (t >> 7) * 16;
            const float* vsrc = proj + (size_t)(j * 64) * P3 + vcol + c;
#pragma unroll
            for (int it = 0; it < 16; it++) {
                const int rp = rp0 + it;
                const float v0 = vsrc[(size_t)(2 * rp) * P3];
                const float v1 = vsrc[(size_t)(2 * rp + 1) * P3];
                uint32_t hp, lp;
                split_pair(v0, v1, hp, lp);
                Vth[c * 36 + rp] = hp;
                Vtl[c * 36 + rp] = lp;
            }
        }
        __syncthreads();

        float sacc[8][4];
#pragma unroll
        for (int nt = 0; nt < 8; nt++)
#pragma unroll
            for (int q = 0; q < 4; q++) sacc[nt][q] = 0.f;

        const uint32_t* q0 = Qh + (w * 16 + g) * 68;
        const uint32_t* q1 = q0 + 8 * 68;
        const uint32_t* q0l = Ql + (w * 16 + g) * 68;
        const uint32_t* q1l = q0l + 8 * 68;
#pragma unroll
        for (int kc = 0; kc < 8; kc++) {
            const int kw = kc * 8;
            uint32_t ah0 = q0[kw + cc], ah1 = q1[kw + cc];
            uint32_t ah2 = q0[kw + cc + 4], ah3 = q1[kw + cc + 4];
            uint32_t al0 = q0l[kw + cc], al1 = q1l[kw + cc];
            uint32_t al2 = q0l[kw + cc + 4], al3 = q1l[kw + cc + 4];
#pragma unroll
            for (int nt = 0; nt < 8; nt++) {
                const int nw = (nt * 8 + g) * 68 + kw;
                uint32_t bh0 = Kh[nw + cc], bh1 = Kh[nw + cc + 4];
                uint32_t bl0 = Kl[nw + cc], bl1 = Kl[nw + cc + 4];
                mma_bf16(sacc[nt][0], sacc[nt][1], sacc[nt][2], sacc[nt][3],
                         ah0, ah1, ah2, ah3, bh0, bh1);
                mma_bf16(sacc[nt][0], sacc[nt][1], sacc[nt][2], sacc[nt][3],
                         ah0, ah1, ah2, ah3, bl0, bl1);
                mma_bf16(sacc[nt][0], sacc[nt][1], sacc[nt][2], sacc[nt][3],
                         al0, al1, al2, al3, bh0, bh1);
            }
        }
        {
            const bool diagt = (j * 64 + 63 > qbase);
            if (diagt) {
                const int r0g = qbase + w * 16 + g;
#pragma unroll
                for (int nt = 0; nt < 8; nt++) {
                    const int cg = j * 64 + nt * 8 + 2 * cc;
                    if (cg     > r0g)     sacc[nt][0] = -1.0e9f;
                    if (cg + 1 > r0g)     sacc[nt][1] = -1.0e9f;
                    if (cg     > r0g + 8) sacc[nt][2] = -1.0e9f;
                    if (cg + 1 > r0g + 8) sacc[nt][3] = -1.0e9f;
                }
            }
        }
        {
            float m0 = -3.0e38f, m1 = -3.0e38f;
#pragma unroll
            for (int nt = 0; nt < 8; nt++) {
                m0 = fmaxf(m0, fmaxf(sacc[nt][0], sacc[nt][1]));
                m1 = fmaxf(m1, fmaxf(sacc[nt][2], sacc[nt][3]));
            }
            m0 = fmaxf(m0, __shfl_xor_sync(0xFFFFFFFFu, m0, 1));
            m0 = fmaxf(m0, __shfl_xor_sync(0xFFFFFFFFu, m0, 2));
            m1 = fmaxf(m1, __shfl_xor_sync(0xFFFFFFFFu, m1, 1));
            m1 = fmaxf(m1, __shfl_xor_sync(0xFFFFFFFFu, m1, 2));
            const float mn0 = fmaxf(rowM0, m0), mn1 = fmaxf(rowM1, m1);
            const float al0 = __expf(rowM0 - mn0), al1 = __expf(rowM1 - mn1);
            rowM0 = mn0; rowM1 = mn1;
            float s0 = 0.f, s1 = 0.f;
#pragma unroll
            for (int nt = 0; nt < 8; nt++) {
                sacc[nt][0] = __expf(sacc[nt][0] - mn0);
                sacc[nt][1] = __expf(sacc[nt][1] - mn0);
                sacc[nt][2] = __expf(sacc[nt][2] - mn1);
                sacc[nt][3] = __expf(sacc[nt][3] - mn1);
                s0 += sacc[nt][0] + sacc[nt][1];
                s1 += sacc[nt][2] + sacc[nt][3];
            }
            s0 += __shfl_xor_sync(0xFFFFFFFFu, s0, 1);
            s0 += __shfl_xor_sync(0xFFFFFFFFu, s0, 2);
            s1 += __shfl_xor_sync(0xFFFFFFFFu, s1, 1);
            s1 += __shfl_xor_sync(0xFFFFFFFFu, s1, 2);
            rowL0 = rowL0 * al0 + s0;
            rowL1 = rowL1 * al1 + s1;
#pragma unroll
            for (int nt = 0; nt < 16; nt++) {
                oacc[nt][0] *= al0; oacc[nt][1] *= al0;
                oacc[nt][2] *= al1; oacc[nt][3] *= al1;
            }
        }
#pragma unroll
        for (int kc = 0; kc < 4; kc++) {
            uint32_t ah0, ah1, ah2, ah3, pl0, pl1, pl2, pl3;
            split_pair(sacc[2 * kc][0],     sacc[2 * kc][1],     ah0, pl0);
            split_pair(sacc[2 * kc][2],     sacc[2 * kc][3],     ah1, pl1);
            split_pair(sacc[2 * kc + 1][0], sacc[2 * kc + 1][1], ah2, pl2);
            split_pair(sacc[2 * kc + 1][2], sacc[2 * kc + 1][3], ah3, pl3);
            const int kw = kc * 8;
#pragma unroll
            for (int nt = 0; nt < 16; nt++) {
                const int nw = (nt * 8 + g) * 36 + kw;
                uint32_t bh0 = Vth[nw + cc], bh1 = Vth[nw + cc + 4];
                uint32_t bl0 = Vtl[nw + cc], bl1 = Vtl[nw + cc + 4];
                mma_bf16(oacc[nt][0], oacc[nt][1], oacc[nt][2], oacc[nt][3],
                         ah0, ah1, ah2, ah3, bh0, bh1);
                mma_bf16(oacc[nt][0], oacc[nt][1], oacc[nt][2], oacc[nt][3],
                         ah0, ah1, ah2, ah3, bl0, bl1);
                mma_bf16(oacc[nt][0], oacc[nt][1], oacc[nt][2], oacc[nt][3],
                         pl0, pl1, pl2, pl3, bh0, bh1);
            }
        }
    }

    {
        const float il0 = 1.0f / rowL0;
        const float il1 = 1.0f / rowL1;
        const size_t base0 = (size_t)(qbase + w * 16 + g) * HID + h * HD + 2 * cc;
#pragma unroll
        for (int nt = 0; nt < 16; nt++) {
            __half2 h0 = __floats2half2_rn(oacc[nt][0] * il0, oacc[nt][1] * il0);
            __half2 h1 = __floats2half2_rn(oacc[nt][2] * il1, oacc[nt][3] * il1);
            *(__half2*)(attn_out_h + base0 + nt * 8) = h0;
            *(__half2*)(attn_out_h + base0 + 8 * HID + nt * 8) = h1;
        }
    }
}

// ---------------- launch ----------------
extern "C" void kernel_launch(void* const* d_in, const int* in_sizes, int n_in,
                              void* d_out, int out_size) {
    (void)in_sizes; (void)n_in; (void)out_size;
    const float* hidden  = (const float*)d_in[0];
    const int*   pos_ids = (const int*)d_in[2];
    const float* W_pack  = (const float*)d_in[3];
    const float* W_o     = (const float*)d_in[4];
    float* out = (float*)d_out;

    float *proj = nullptr;
    __half *hid_h = nullptr, *wp_h = nullptr, *wo_h = nullptr, *attn_h = nullptr;
    cudaGetSymbolAddress((void**)&proj, g_proj);
    cudaGetSymbolAddress((void**)&hid_h, g_hid_h);
    cudaGetSymbolAddress((void**)&wp_h, g_wp_h);
    cudaGetSymbolAddress((void**)&wo_h, g_wo_h);
    cudaGetSymbolAddress((void**)&attn_h, g_attn_h);
    cudaFuncSetAttribute(attn_reg, cudaFuncAttributeMaxDynamicSharedMemorySize, ATTN3_SMEM);
    cudaFuncSetAttribute(gemm_fp16ca, cudaFuncAttributeMaxDynamicSharedMemorySize, GEMM_SMEM);

    // converts (bandwidth-bound)
    f2h_kernel<<<(S_LEN * HID) / (256 * 8), 256>>>(hidden, hid_h, S_LEN * HID);
    f2h_kernel<<<(P3 * HID) / (256 * 8), 256>>>(W_pack, wp_h, P3 * HID);
    f2h_kernel<<<(HID * HID) / (256 * 8), 256>>>(W_o, wo_h, HID * HID);

    // 1) QKV projection (fp16 cp.async + ldmatrix, 2 CTAs/SM)
    gemm_fp16ca<<<dim3(P3 / 128, S_LEN / 128), 128, GEMM_SMEM>>>(hid_h, wp_h, proj,
                                                                 S_LEN, P3, HID);
    // 2) RoPE in-place on Q,K
    rope2_kernel<<<S_LEN, 256>>>(proj, pos_ids);
    // 3) causal flash attention (register-resident softmax, writes fp16)
    attn_reg<<<dim3(NH, S_LEN / 128), 256, ATTN3_SMEM>>>(proj, attn_h);
    // 4) output projection
    gemm_fp16ca<<<dim3(HID / 128, S_LEN / 128), 128, GEMM_SMEM>>>(attn_h, wo_h, out,
                                                                  S_LEN, HID, HID);
}

// round 17
// speedup vs baseline: 1.3085x; 1.3085x over previous
#include <cuda_runtime.h>
#include <cuda_fp16.h>
#include <cstdint>
#include <cstddef>

#define S_LEN 2048
#define HID   4096
#define NH    32
#define HD    128
#define P3    12288   // 3*HID
#define NORM  0.08838834764831845f   // 1/sqrt(128)

// ---------------- scratch (no allocations allowed) ----------------
__device__ float    g_proj[S_LEN * P3];
__device__ __half   g_hid_h[S_LEN * HID];
__device__ __half   g_wp_h[P3 * HID];
__device__ __half   g_wo_h[HID * HID];
__device__ __half   g_attn_h[S_LEN * HID];
// pre-split bf16 hi/lo operands for attention (packed pairs as uint32)
__device__ uint32_t g_qh[NH * S_LEN * 64];
__device__ uint32_t g_ql[NH * S_LEN * 64];
__device__ uint32_t g_kh[NH * S_LEN * 64];
__device__ uint32_t g_kl[NH * S_LEN * 64];
__device__ uint32_t g_vth[NH * 32 * 128 * 32];
__device__ uint32_t g_vtl[NH * 32 * 128 * 32];

// ---------------- helpers ----------------
__device__ __forceinline__ uint32_t smem_u32(const void* p) {
    uint32_t a;
    asm("{ .reg .u64 t; cvta.to.shared.u64 t, %1; cvt.u32.u64 %0, t; }" : "=r"(a) : "l"(p));
    return a;
}
__device__ __forceinline__ void cp16(uint32_t saddr, const void* gptr) {
    asm volatile("cp.async.ca.shared.global [%0], [%1], 16;" :: "r"(saddr), "l"(gptr));
}
#define CP_COMMIT() asm volatile("cp.async.commit_group;" ::: "memory")
#define CP_WAIT(n)  asm volatile("cp.async.wait_group %0;" :: "n"(n) : "memory")

__device__ __forceinline__ void ldsm4(uint32_t& r0, uint32_t& r1, uint32_t& r2, uint32_t& r3,
                                      uint32_t addr) {
    asm volatile("ldmatrix.sync.aligned.m8n8.x4.shared.b16 {%0,%1,%2,%3}, [%4];"
                 : "=r"(r0), "=r"(r1), "=r"(r2), "=r"(r3) : "r"(addr));
}

__device__ __forceinline__ void mma_fp16(float& c0, float& c1, float& c2, float& c3,
                                         uint32_t a0, uint32_t a1, uint32_t a2, uint32_t a3,
                                         uint32_t b0, uint32_t b1) {
    asm volatile(
        "mma.sync.aligned.m16n8k16.row.col.f32.f16.f16.f32 "
        "{%0,%1,%2,%3}, {%4,%5,%6,%7}, {%8,%9}, {%0,%1,%2,%3};"
        : "+f"(c0), "+f"(c1), "+f"(c2), "+f"(c3)
        : "r"(a0), "r"(a1), "r"(a2), "r"(a3), "r"(b0), "r"(b1));
}
__device__ __forceinline__ void mma_bf16(float& c0, float& c1, float& c2, float& c3,
                                         uint32_t a0, uint32_t a1, uint32_t a2, uint32_t a3,
                                         uint32_t b0, uint32_t b1) {
    asm volatile(
        "mma.sync.aligned.m16n8k16.row.col.f32.bf16.bf16.f32 "
        "{%0,%1,%2,%3}, {%4,%5,%6,%7}, {%8,%9}, {%0,%1,%2,%3};"
        : "+f"(c0), "+f"(c1), "+f"(c2), "+f"(c3)
        : "r"(a0), "r"(a1), "r"(a2), "r"(a3), "r"(b0), "r"(b1));
}
__device__ __forceinline__ void split_pair(float x0, float x1, uint32_t& hp, uint32_t& lp) {
    uint16_t h0, h1, l0, l1;
    asm("cvt.rn.bf16.f32 %0, %1;" : "=h"(h0) : "f"(x0));
    asm("cvt.rn.bf16.f32 %0, %1;" : "=h"(h1) : "f"(x1));
    float r0 = x0 - __uint_as_float((uint32_t)h0 << 16);
    float r1 = x1 - __uint_as_float((uint32_t)h1 << 16);
    asm("cvt.rn.bf16.f32 %0, %1;" : "=h"(l0) : "f"(r0));
    asm("cvt.rn.bf16.f32 %0, %1;" : "=h"(l1) : "f"(r1));
    asm("mov.b32 %0, {%1, %2};" : "=r"(hp) : "h"(h0), "h"(h1));
    asm("mov.b32 %0, {%1, %2};" : "=r"(lp) : "h"(l0), "h"(l1));
}

// ---------------- fp32 -> fp16 convert ----------------
__global__ __launch_bounds__(256) void f2h_kernel(const float* __restrict__ src,
                                                  __half* __restrict__ dst, int n) {
    int i = (blockIdx.x * blockDim.x + threadIdx.x) * 8;
    if (i >= n) return;
    float4 a = *(const float4*)(src + i);
    float4 b = *(const float4*)(src + i + 4);
    __half2 h0 = __floats2half2_rn(a.x, a.y);
    __half2 h1 = __floats2half2_rn(a.z, a.w);
    __half2 h2 = __floats2half2_rn(b.x, b.y);
    __half2 h3 = __floats2half2_rn(b.z, b.w);
    uint4 v = {*(uint32_t*)&h0, *(uint32_t*)&h1, *(uint32_t*)&h2, *(uint32_t*)&h3};
    *(uint4*)(dst + i) = v;
}

// ---------------- fp16 cp.async + ldmatrix GEMM: C = A * B^T (R14 config) ----------------
#define KW    20
#define NSTG  4
#define AW    (128 * KW)
#define STGW  ((128 + 256) * KW)
#define GEMM_SMEM (NSTG * STGW * 4)            // 122880 B

__global__ __launch_bounds__(256, 1) void gemm_fp16ca(const __half* __restrict__ A,
                                                      const __half* __restrict__ B,
                                                      float* __restrict__ C,
                                                      int M, int N, int K) {
    extern __shared__ uint32_t sm[];
    const int t = threadIdx.x;
    const int w = t >> 5, lane = t & 31;
    const int wm = w >> 2, wn = w & 3;
    const int g = lane >> 2, cc = lane & 3;
    const int m0 = blockIdx.y * 128, n0 = blockIdx.x * 256;
    const int KT = K >> 5;
    const uint32_t sbase = smem_u32(sm);

    const int ar = t >> 1, ac = (t & 1) * 2;
    const __half* AgA = A + (size_t)(m0 + ar) * K + ac * 8;
    const uint32_t saA = sbase + (ar * KW + ac * 4) * 4;
    const int br = t >> 2, bc = t & 3;
    const __half* BgB = B + (size_t)(n0 + br) * K + bc * 8;
    const uint32_t saB = sbase + AW * 4 + (br * KW + bc * 4) * 4;

    const int lrow = lane & 7, sel = lane >> 3;
    uint32_t a_woff[4], b_woff[4];
#pragma unroll
    for (int mt = 0; mt < 4; mt++)
        a_woff[mt] = (uint32_t)((wm * 64 + mt * 16 + lrow + (sel & 1) * 8) * KW +
                                (sel >> 1) * 4);
#pragma unroll
    for (int p = 0; p < 4; p++)
        b_woff[p] = (uint32_t)(AW + (wn * 64 + p * 16 + (sel >> 1) * 8 + lrow) * KW +
                               (sel & 1) * 4);

#pragma unroll
    for (int s = 0; s < NSTG - 1; s++) {
        const uint32_t so = s * STGW * 4;
        const size_t ko = (size_t)s * 32;
        cp16(saA + so, AgA + ko);
        cp16(saA + so + 16, AgA + ko + 8);
#pragma unroll
        for (int j = 0; j < 4; j++)
            cp16(saB + so + j * (64 * KW * 4), BgB + (size_t)(64 * j) * K + ko);
        CP_COMMIT();
    }

    float acc[4][8][4];
#pragma unroll
    for (int mt = 0; mt < 4; mt++)
#pragma unroll
        for (int nt = 0; nt < 8; nt++)
#pragma unroll
            for (int q = 0; q < 4; q++) acc[mt][nt][q] = 0.f;

    for (int kt = 0; kt < KT; kt++) {
        CP_WAIT(2);
        __syncthreads();
        if (kt + NSTG - 1 < KT) {
            const uint32_t so = ((kt + NSTG - 1) % NSTG) * STGW * 4;
            const size_t ko = (size_t)(kt + NSTG - 1) * 32;
            cp16(saA + so, AgA + ko);
            cp16(saA + so + 16, AgA + ko + 8);
#pragma unroll
            for (int j = 0; j < 4; j++)
                cp16(saB + so + j * (64 * KW * 4), BgB + (size_t)(64 * j) * K + ko);
        }
        CP_COMMIT();

        const uint32_t stgoff = sbase + ((kt % NSTG) * STGW) * 4;
#pragma unroll
        for (int hh = 0; hh < 2; hh++) {
            const uint32_t kwb = stgoff + hh * 8 * 4;
            uint32_t af[4][4], bf[4][4];
#pragma unroll
            for (int mt = 0; mt < 4; mt++)
                ldsm4(af[mt][0], af[mt][1], af[mt][2], af[mt][3], kwb + a_woff[mt] * 4);
#pragma unroll
            for (int p = 0; p < 4; p++)
                ldsm4(bf[p][0], bf[p][1], bf[p][2], bf[p][3], kwb + b_woff[p] * 4);
#pragma unroll
            for (int mt = 0; mt < 4; mt++)
#pragma unroll
                for (int nt = 0; nt < 8; nt++)
                    mma_fp16(acc[mt][nt][0], acc[mt][nt][1], acc[mt][nt][2], acc[mt][nt][3],
                             af[mt][0], af[mt][1], af[mt][2], af[mt][3],
                             bf[nt >> 1][(nt & 1) * 2], bf[nt >> 1][(nt & 1) * 2 + 1]);
        }
    }

#pragma unroll
    for (int mt = 0; mt < 4; mt++) {
        const int r = m0 + wm * 64 + mt * 16 + g;
#pragma unroll
        for (int nt = 0; nt < 8; nt++) {
            const int n = n0 + wn * 64 + nt * 8 + 2 * cc;
            *(float2*)&C[(size_t)r * N + n]       = make_float2(acc[mt][nt][0], acc[mt][nt][1]);
            *(float2*)&C[(size_t)(r + 8) * N + n] = make_float2(acc[mt][nt][2], acc[mt][nt][3]);
        }
    }
}

// ---------------- RoPE ----------------
__global__ __launch_bounds__(256) void rope2_kernel(float* __restrict__ proj,
                                                    const int* __restrict__ pos_ids) {
    __shared__ float ca[64], sa[64];
    const int s = blockIdx.x;
    const int t = threadIdx.x;
    if (t < 64) {
        const int pos = pos_ids[s];
        double inv = exp(-((double)t / 64.0) * 9.210340371976184);
        double a = (double)pos * inv;
        const double twopi = 6.283185307179586476925286766559;
        a -= floor(a / twopi) * twopi;
        sa[t] = sinf((float)a);
        ca[t] = cosf((float)a);
    }
    __syncthreads();
    float* base = proj + (size_t)s * P3;
#pragma unroll
    for (int it = 0; it < 16; it++) {
        const int p = t + it * 256;
        const int d = p & 63;
        const int hh = (p >> 6) & 31;
        float* ptr = base + ((p >> 11) ? HID : 0) + hh * HD + d;
        const float x1 = ptr[0], x2 = ptr[64];
        const float c = ca[d], sn = sa[d];
        ptr[0]  = x1 * c - x2 * sn;
        ptr[64] = x2 * c + x1 * sn;
    }
}

// ---------------- prep: split roped Q(xNORM)/K/V into bf16 hi/lo layouts ----------------
// grid (NH, 32 tiles of 64 rows), 256 threads.
__global__ __launch_bounds__(256) void prep_kernel(const float* __restrict__ proj,
                                                   uint32_t* __restrict__ gqh,
                                                   uint32_t* __restrict__ gql,
                                                   uint32_t* __restrict__ gkh,
                                                   uint32_t* __restrict__ gkl,
                                                   uint32_t* __restrict__ gvth,
                                                   uint32_t* __restrict__ gvtl) {
    const int t = threadIdx.x;
    const int h = blockIdx.x, tile = blockIdx.y;

    // Q and K: thread handles row r (64 rows), 32 cols
    {
        const int r = t >> 2, c0 = (t & 3) * 32;
        const int s = tile * 64 + r;
        const float* qsrc = proj + (size_t)s * P3 + h * HD + c0;
        const float* ksrc = proj + (size_t)s * P3 + HID + h * HD + c0;
        uint32_t* qh = gqh + ((size_t)h * S_LEN + s) * 64 + (c0 >> 1);
        uint32_t* ql = gql + ((size_t)h * S_LEN + s) * 64 + (c0 >> 1);
        uint32_t* kh = gkh + ((size_t)h * S_LEN + s) * 64 + (c0 >> 1);
        uint32_t* kl = gkl + ((size_t)h * S_LEN + s) * 64 + (c0 >> 1);
#pragma unroll
        for (int i = 0; i < 8; i++) {
            float4 v = *(const float4*)(qsrc + i * 4);
            uint32_t hp, lp;
            split_pair(v.x * NORM, v.y * NORM, hp, lp);
            qh[2 * i] = hp; ql[2 * i] = lp;
            split_pair(v.z * NORM, v.w * NORM, hp, lp);
            qh[2 * i + 1] = hp; ql[2 * i + 1] = lp;
            float4 k = *(const float4*)(ksrc + i * 4);
            split_pair(k.x, k.y, hp, lp);
            kh[2 * i] = hp; kl[2 * i] = lp;
            split_pair(k.z, k.w, hp, lp);
            kh[2 * i + 1] = hp; kl[2 * i + 1] = lp;
        }
    }
    // V transpose: thread handles dim c, 16 kv-pairs
    {
        const int c = (t & 31) + ((t >> 5) & 3) * 32;
        const int rp0 = (t >> 7) * 16;
        const float* vsrc = proj + (size_t)(tile * 64) * P3 + 2 * HID + h * HD + c;
        uint32_t* vh = gvth + (((size_t)h * 32 + tile) * 128 + c) * 32;
        uint32_t* vl = gvtl + (((size_t)h * 32 + tile) * 128 + c) * 32;
#pragma unroll
        for (int it = 0; it < 16; it++) {
            const int rp = rp0 + it;
            const float v0 = vsrc[(size_t)(2 * rp) * P3];
            const float v1 = vsrc[(size_t)(2 * rp + 1) * P3];
            uint32_t hp, lp;
            split_pair(v0, v1, hp, lp);
            vh[rp] = hp;
            vl[rp] = lp;
        }
    }
}

// ---------------- attention: pre-split operands, cp.async double-buffered ----------------
#define OFF_QH  0
#define OFF_QL  34816
#define OFF_K0  69632                 // Kh then Kl (17408 each) per buffer; buffers 34816 apart
#define OFF_V0  139264                // Vth then Vtl (18432 each) per buffer; buffers 36864 apart
#define ATTN4_SMEM 212992

__global__ __launch_bounds__(256, 1) void attn_pre(const uint32_t* __restrict__ gqh,
                                                   const uint32_t* __restrict__ gql,
                                                   const uint32_t* __restrict__ gkh,
                                                   const uint32_t* __restrict__ gkl,
                                                   const uint32_t* __restrict__ gvth,
                                                   const uint32_t* __restrict__ gvtl,
                                                   __half* __restrict__ attn_out_h) {
    extern __shared__ char smraw[];
    const uint32_t sbase = smem_u32(smraw);
    const int t = threadIdx.x;
    const int w = t >> 5, lane = t & 31;
    const int g = lane >> 2, cc = lane & 3;
    const int h = blockIdx.x;
    const int qt = 15 - (int)blockIdx.y;
    const int qbase = qt * 128;

    // per-thread cp.async slot constants
    const int kr = t >> 2, kq = (t & 3) * 16;            // K: row, word offset
    const uint32_t kdst = (uint32_t)((kr * 68 + kq) * 4);
    const int vc = t >> 1, vhf = (t & 1) * 16;           // V: dim, word offset
    const uint32_t vdst = (uint32_t)((vc * 36 + vhf) * 4);

    // prologue: Q + tile 0 in one group
    {
        const int r = t >> 1, half = (t & 1) * 32;
        const size_t gq = ((size_t)h * S_LEN + qbase + r) * 64 + half;
        const uint32_t dq  = sbase + OFF_QH + (uint32_t)((r * 68 + half) * 4);
        const uint32_t dql = sbase + OFF_QL + (uint32_t)((r * 68 + half) * 4);
#pragma unroll
        for (int c = 0; c < 8; c++) {
            cp16(dq + c * 16, gqh + gq + c * 4);
            cp16(dql + c * 16, gql + gq + c * 4);
        }
        const size_t gk = ((size_t)h * S_LEN + kr) * 64 + kq;
        const uint32_t kb = sbase + OFF_K0 + kdst;
#pragma unroll
        for (int c = 0; c < 4; c++) {
            cp16(kb + c * 16, gkh + gk + c * 4);
            cp16(kb + 17408 + c * 16, gkl + gk + c * 4);
        }
        const size_t gv = ((size_t)h * 32 * 128 + vc) * 32 + vhf;
        const uint32_t vb = sbase + OFF_V0 + vdst;
#pragma unroll
        for (int c = 0; c < 4; c++) {
            cp16(vb + c * 16, gvth + gv + c * 4);
            cp16(vb + 18432 + c * 16, gvtl + gv + c * 4);
        }
        CP_COMMIT();
    }

    float rowM0 = -3.0e38f, rowM1 = -3.0e38f, rowL0 = 0.f, rowL1 = 0.f;
    float oacc[16][4];
#pragma unroll
    for (int nt = 0; nt < 16; nt++)
#pragma unroll
        for (int q = 0; q < 4; q++) oacc[nt][q] = 0.f;

    const int nkt = 2 * qt + 2;
    for (int j = 0; j < nkt; j++) {
        __syncthreads();   // all threads done with buffer (j+1)&1 from iteration j-1
        if (j + 1 < nkt) {
            const int pj = (j + 1) & 1;
            const size_t gk = ((size_t)h * S_LEN + (j + 1) * 64 + kr) * 64 + kq;
            const uint32_t kb = sbase + OFF_K0 + pj * 34816 + kdst;
#pragma unroll
            for (int c = 0; c < 4; c++) {
                cp16(kb + c * 16, gkh + gk + c * 4);
                cp16(kb + 17408 + c * 16, gkl + gk + c * 4);
            }
            const size_t gv = (((size_t)h * 32 + (j + 1)) * 128 + vc) * 32 + vhf;
            const uint32_t vb = sbase + OFF_V0 + pj * 36864 + vdst;
#pragma unroll
            for (int c = 0; c < 4; c++) {
                cp16(vb + c * 16, gvth + gv + c * 4);
                cp16(vb + 18432 + c * 16, gvtl + gv + c * 4);
            }
        }
        CP_COMMIT();
        CP_WAIT(1);        // tile j (and Q) complete; tile j+1 may be in flight
        __syncthreads();

        const uint32_t* Qh  = (const uint32_t*)(smraw + OFF_QH);
        const uint32_t* Ql  = (const uint32_t*)(smraw + OFF_QL);
        const uint32_t* Kh  = (const uint32_t*)(smraw + OFF_K0 + (j & 1) * 34816);
        const uint32_t* Kl  = Kh + 17408 / 4;
        const uint32_t* Vth = (const uint32_t*)(smraw + OFF_V0 + (j & 1) * 36864);
        const uint32_t* Vtl = Vth + 18432 / 4;

        // ---- scores (3-MMA bf16 split) ----
        float sacc[8][4];
#pragma unroll
        for (int nt = 0; nt < 8; nt++)
#pragma unroll
            for (int q = 0; q < 4; q++) sacc[nt][q] = 0.f;

        const uint32_t* q0 = Qh + (w * 16 + g) * 68;
        const uint32_t* q1 = q0 + 8 * 68;
        const uint32_t* q0l = Ql + (w * 16 + g) * 68;
        const uint32_t* q1l = q0l + 8 * 68;
#pragma unroll
        for (int kc = 0; kc < 8; kc++) {
            const int kw = kc * 8;
            uint32_t ah0 = q0[kw + cc], ah1 = q1[kw + cc];
            uint32_t ah2 = q0[kw + cc + 4], ah3 = q1[kw + cc + 4];
            uint32_t al0 = q0l[kw + cc], al1 = q1l[kw + cc];
            uint32_t al2 = q0l[kw + cc + 4], al3 = q1l[kw + cc + 4];
#pragma unroll
            for (int nt = 0; nt < 8; nt++) {
                const int nw = (nt * 8 + g) * 68 + kw;
                uint32_t bh0 = Kh[nw + cc], bh1 = Kh[nw + cc + 4];
                uint32_t bl0 = Kl[nw + cc], bl1 = Kl[nw + cc + 4];
                mma_bf16(sacc[nt][0], sacc[nt][1], sacc[nt][2], sacc[nt][3],
                         ah0, ah1, ah2, ah3, bh0, bh1);
                mma_bf16(sacc[nt][0], sacc[nt][1], sacc[nt][2], sacc[nt][3],
                         ah0, ah1, ah2, ah3, bl0, bl1);
                mma_bf16(sacc[nt][0], sacc[nt][1], sacc[nt][2], sacc[nt][3],
                         al0, al1, al2, al3, bh0, bh1);
            }
        }
        // ---- causal mask ----
        {
            const bool diagt = (j * 64 + 63 > qbase);
            if (diagt) {
                const int r0g = qbase + w * 16 + g;
#pragma unroll
                for (int nt = 0; nt < 8; nt++) {
                    const int cg = j * 64 + nt * 8 + 2 * cc;
                    if (cg     > r0g)     sacc[nt][0] = -1.0e9f;
                    if (cg + 1 > r0g)     sacc[nt][1] = -1.0e9f;
                    if (cg     > r0g + 8) sacc[nt][2] = -1.0e9f;
                    if (cg + 1 > r0g + 8) sacc[nt][3] = -1.0e9f;
                }
            }
        }
        // ---- in-register online softmax ----
        {
            float m0 = -3.0e38f, m1 = -3.0e38f;
#pragma unroll
            for (int nt = 0; nt < 8; nt++) {
                m0 = fmaxf(m0, fmaxf(sacc[nt][0], sacc[nt][1]));
                m1 = fmaxf(m1, fmaxf(sacc[nt][2], sacc[nt][3]));
            }
            m0 = fmaxf(m0, __shfl_xor_sync(0xFFFFFFFFu, m0, 1));
            m0 = fmaxf(m0, __shfl_xor_sync(0xFFFFFFFFu, m0, 2));
            m1 = fmaxf(m1, __shfl_xor_sync(0xFFFFFFFFu, m1, 1));
            m1 = fmaxf(m1, __shfl_xor_sync(0xFFFFFFFFu, m1, 2));
            const float mn0 = fmaxf(rowM0, m0), mn1 = fmaxf(rowM1, m1);
            const float al0 = __expf(rowM0 - mn0), al1 = __expf(rowM1 - mn1);
            rowM0 = mn0; rowM1 = mn1;
            float s0 = 0.f, s1 = 0.f;
#pragma unroll
            for (int nt = 0; nt < 8; nt++) {
                sacc[nt][0] = __expf(sacc[nt][0] - mn0);
                sacc[nt][1] = __expf(sacc[nt][1] - mn0);
                sacc[nt][2] = __expf(sacc[nt][2] - mn1);
                sacc[nt][3] = __expf(sacc[nt][3] - mn1);
                s0 += sacc[nt][0] + sacc[nt][1];
                s1 += sacc[nt][2] + sacc[nt][3];
            }
            s0 += __shfl_xor_sync(0xFFFFFFFFu, s0, 1);
            s0 += __shfl_xor_sync(0xFFFFFFFFu, s0, 2);
            s1 += __shfl_xor_sync(0xFFFFFFFFu, s1, 1);
            s1 += __shfl_xor_sync(0xFFFFFFFFu, s1, 2);
            rowL0 = rowL0 * al0 + s0;
            rowL1 = rowL1 * al1 + s1;
#pragma unroll
            for (int nt = 0; nt < 16; nt++) {
                oacc[nt][0] *= al0; oacc[nt][1] *= al0;
                oacc[nt][2] *= al1; oacc[nt][3] *= al1;
            }
        }
        // ---- PV ----
#pragma unroll
        for (int kc = 0; kc < 4; kc++) {
            uint32_t ah0, ah1, ah2, ah3, pl0, pl1, pl2, pl3;
            split_pair(sacc[2 * kc][0],     sacc[2 * kc][1],     ah0, pl0);
            split_pair(sacc[2 * kc][2],     sacc[2 * kc][3],     ah1, pl1);
            split_pair(sacc[2 * kc + 1][0], sacc[2 * kc + 1][1], ah2, pl2);
            split_pair(sacc[2 * kc + 1][2], sacc[2 * kc + 1][3], ah3, pl3);
            const int kw = kc * 8;
#pragma unroll
            for (int nt = 0; nt < 16; nt++) {
                const int nw = (nt * 8 + g) * 36 + kw;
                uint32_t bh0 = Vth[nw + cc], bh1 = Vth[nw + cc + 4];
                uint32_t bl0 = Vtl[nw + cc], bl1 = Vtl[nw + cc + 4];
                mma_bf16(oacc[nt][0], oacc[nt][1], oacc[nt][2], oacc[nt][3],
                         ah0, ah1, ah2, ah3, bh0, bh1);
                mma_bf16(oacc[nt][0], oacc[nt][1], oacc[nt][2], oacc[nt][3],
                         ah0, ah1, ah2, ah3, bl0, bl1);
                mma_bf16(oacc[nt][0], oacc[nt][1], oacc[nt][2], oacc[nt][3],
                         pl0, pl1, pl2, pl3, bh0, bh1);
            }
        }
    }

    // ---- epilogue: O /= L, write fp16 ----
    {
        const float il0 = 1.0f / rowL0;
        const float il1 = 1.0f / rowL1;
        const size_t base0 = (size_t)(qbase + w * 16 + g) * HID + h * HD + 2 * cc;
#pragma unroll
        for (int nt = 0; nt < 16; nt++) {
            __half2 h0 = __floats2half2_rn(oacc[nt][0] * il0, oacc[nt][1] * il0);
            __half2 h1 = __floats2half2_rn(oacc[nt][2] * il1, oacc[nt][3] * il1);
            *(__half2*)(attn_out_h + base0 + nt * 8) = h0;
            *(__half2*)(attn_out_h + base0 + 8 * HID + nt * 8) = h1;
        }
    }
}

// ---------------- launch ----------------
extern "C" void kernel_launch(void* const* d_in, const int* in_sizes, int n_in,
                              void* d_out, int out_size) {
    (void)in_sizes; (void)n_in; (void)out_size;
    const float* hidden  = (const float*)d_in[0];
    const int*   pos_ids = (const int*)d_in[2];
    const float* W_pack  = (const float*)d_in[3];
    const float* W_o     = (const float*)d_in[4];
    float* out = (float*)d_out;

    float *proj = nullptr;
    __half *hid_h = nullptr, *wp_h = nullptr, *wo_h = nullptr, *attn_h = nullptr;
    uint32_t *qh, *ql, *kh, *kl, *vth, *vtl;
    cudaGetSymbolAddress((void**)&proj, g_proj);
    cudaGetSymbolAddress((void**)&hid_h, g_hid_h);
    cudaGetSymbolAddress((void**)&wp_h, g_wp_h);
    cudaGetSymbolAddress((void**)&wo_h, g_wo_h);
    cudaGetSymbolAddress((void**)&attn_h, g_attn_h);
    cudaGetSymbolAddress((void**)&qh, g_qh);
    cudaGetSymbolAddress((void**)&ql, g_ql);
    cudaGetSymbolAddress((void**)&kh, g_kh);
    cudaGetSymbolAddress((void**)&kl, g_kl);
    cudaGetSymbolAddress((void**)&vth, g_vth);
    cudaGetSymbolAddress((void**)&vtl, g_vtl);
    cudaFuncSetAttribute(attn_pre, cudaFuncAttributeMaxDynamicSharedMemorySize, ATTN4_SMEM);
    cudaFuncSetAttribute(gemm_fp16ca, cudaFuncAttributeMaxDynamicSharedMemorySize, GEMM_SMEM);

    // converts (bandwidth-bound)
    f2h_kernel<<<(S_LEN * HID) / (256 * 8), 256>>>(hidden, hid_h, S_LEN * HID);
    f2h_kernel<<<(P3 * HID) / (256 * 8), 256>>>(W_pack, wp_h, P3 * HID);
    f2h_kernel<<<(HID * HID) / (256 * 8), 256>>>(W_o, wo_h, HID * HID);

    // 1) QKV projection (fp16 cp.async + ldmatrix)
    gemm_fp16ca<<<dim3(P3 / 256, S_LEN / 128), 256, GEMM_SMEM>>>(hid_h, wp_h, proj,
                                                                 S_LEN, P3, HID);
    // 2) RoPE in-place on Q,K
    rope2_kernel<<<S_LEN, 256>>>(proj, pos_ids);
    // 3) pre-split Q/K/V into bf16 hi/lo attention layouts
    prep_kernel<<<dim3(NH, 32), 256>>>(proj, qh, ql, kh, kl, vth, vtl);
    // 4) causal flash attention (cp.async double-buffered, register softmax)
    attn_pre<<<dim3(NH, S_LEN / 128), 256, ATTN4_SMEM>>>(qh, ql, kh, kl, vth, vtl, attn_h);
    // 5) output projection
    gemm_fp16ca<<<dim3(HID / 256, S_LEN / 128), 256, GEMM_SMEM>>>(attn_h, wo_h, out,
                                                                  S_LEN, HID, HID);
}